// round 1
// baseline (speedup 1.0000x reference)
#include <cuda_runtime.h>
#include <math.h>

// ---------------- problem sizes (fixed by the reference) ----------------
#define L_SEQ  2048
#define BATCH  2
#define DM     768
#define DI     1536
#define DS     16
#define M_ROWS (BATCH * L_SEQ)   // 4096
#define N_XZ   (2 * DI)          // 3072
#define N_COMB 1664              // 1536 (W_dt) + 32 (W_x) padded to 13*128

// ---------------- scratch (static device globals; no runtime alloc) ----
__device__ __align__(128) float g_xz[M_ROWS * N_XZ];      // 50.3 MB
__device__ __align__(128) float g_xc[M_ROWS * DI];        // 25.2 MB
__device__ __align__(128) float g_dx[M_ROWS * N_COMB];    // 27.3 MB
__device__ __align__(128) float g_delta[M_ROWS * DI];     // 25.2 MB
__device__ __align__(128) float g_y[M_ROWS * DI];         // 25.2 MB
__device__ __align__(128) float g_wcomb[N_COMB * DI];     // 10.2 MB

// ---------------- generic NT GEMM: C[M,N] = A[M,K] * B[N,K]^T -----------
#define BM 128
#define BN 128
#define BK 16

__global__ __launch_bounds__(256, 2)
void gemm_nt(const float* __restrict__ A, const float* __restrict__ B,
             float* __restrict__ C, int M, int N, int K) {
    __shared__ float As[BK][BM];
    __shared__ float Bs[BK][BN];
    const int bm = blockIdx.y * BM;
    const int bn = blockIdx.x * BN;
    const int t  = threadIdx.x;
    const int tx = t & 15;        // n-dir, 0..15
    const int ty = t >> 4;        // m-dir, 0..15
    const int lr = t >> 2;        // load row 0..63
    const int lk = (t & 3) * 4;   // load k offset 0,4,8,12

    const float* Ag = A + (size_t)bm * K;
    const float* Bg = B + (size_t)bn * K;

    float acc[8][8];
#pragma unroll
    for (int i = 0; i < 8; i++)
#pragma unroll
        for (int j = 0; j < 8; j++) acc[i][j] = 0.f;

    for (int k0 = 0; k0 < K; k0 += BK) {
#pragma unroll
        for (int h = 0; h < 2; h++) {
            int row = lr + h * 64;
            float4 va = *(const float4*)(Ag + (size_t)row * K + k0 + lk);
            As[lk + 0][row] = va.x; As[lk + 1][row] = va.y;
            As[lk + 2][row] = va.z; As[lk + 3][row] = va.w;
            float4 vb = *(const float4*)(Bg + (size_t)row * K + k0 + lk);
            Bs[lk + 0][row] = vb.x; Bs[lk + 1][row] = vb.y;
            Bs[lk + 2][row] = vb.z; Bs[lk + 3][row] = vb.w;
        }
        __syncthreads();
#pragma unroll
        for (int kk = 0; kk < BK; kk++) {
            float a[8], b[8];
            *(float4*)&a[0] = *(const float4*)&As[kk][ty * 4];
            *(float4*)&a[4] = *(const float4*)&As[kk][64 + ty * 4];
            *(float4*)&b[0] = *(const float4*)&Bs[kk][tx * 4];
            *(float4*)&b[4] = *(const float4*)&Bs[kk][64 + tx * 4];
#pragma unroll
            for (int i = 0; i < 8; i++)
#pragma unroll
                for (int j = 0; j < 8; j++)
                    acc[i][j] = fmaf(a[i], b[j], acc[i][j]);
        }
        __syncthreads();
    }
#pragma unroll
    for (int i = 0; i < 8; i++) {
        int row = bm + ((i < 4) ? (ty * 4 + i) : (64 + ty * 4 + (i - 4)));
        float* Cr = C + (size_t)row * N + bn;
        *(float4*)(Cr + tx * 4)      = make_float4(acc[i][0], acc[i][1], acc[i][2], acc[i][3]);
        *(float4*)(Cr + 64 + tx * 4) = make_float4(acc[i][4], acc[i][5], acc[i][6], acc[i][7]);
    }
}

// ---------------- pack [W_dt ; W_x ; zeros] into one (1664,1536) --------
__global__ void pack_w_k(const float* __restrict__ Wdt, const float* __restrict__ Wx) {
    int idx = blockIdx.x * 256 + threadIdx.x;
    if (idx >= N_COMB * DI) return;
    int row = idx / DI;
    int col = idx - row * DI;
    float v = 0.f;
    if (row < DI)            v = Wdt[idx];
    else if (row < DI + 32)  v = Wx[(row - DI) * DI + col];
    g_wcomb[idx] = v;
}

// ---------------- depthwise causal conv (dc=4) + SiLU -------------------
__global__ void conv_silu_k(const float* __restrict__ Wc) {
    int idx = blockIdx.x * 256 + threadIdx.x;
    if (idx >= M_ROWS * DI) return;
    int d = idx % DI;
    int m = idx / DI;
    int l = m & (L_SEQ - 1);
    float w0 = Wc[d * 4 + 0], w1 = Wc[d * 4 + 1], w2 = Wc[d * 4 + 2], w3 = Wc[d * 4 + 3];
    float s = g_xz[(size_t)m * N_XZ + d] * w3;
    if (l >= 1) s = fmaf(g_xz[(size_t)(m - 1) * N_XZ + d], w2, s);
    if (l >= 2) s = fmaf(g_xz[(size_t)(m - 2) * N_XZ + d], w1, s);
    if (l >= 3) s = fmaf(g_xz[(size_t)(m - 3) * N_XZ + d], w0, s);
    g_xc[idx] = __fdividef(s, 1.f + __expf(-s));
}

// ---------------- delta = softplus(delta_pre + b_dt) --------------------
__global__ void softplus_k(const float* __restrict__ bdt) {
    int idx = blockIdx.x * 256 + threadIdx.x;
    if (idx >= M_ROWS * DI) return;
    int d = idx % DI;
    int m = idx / DI;
    float x = g_dx[(size_t)m * N_COMB + d] + bdt[d];
    g_delta[idx] = (x > 20.f) ? x : log1pf(__expf(x));
}

// ---------------- selective scan + D skip + z gating --------------------
// one thread per (b, d) channel; 32-thread blocks; P-deep register prefetch
__global__ __launch_bounds__(32)
void scan_k(const float* __restrict__ Alog, const float* __restrict__ Dp) {
    const int d = blockIdx.x * 32 + threadIdx.x;
    const int b = blockIdx.y;

    float A[DS];
#pragma unroll
    for (int s = 0; s < DS; s++) A[s] = -__expf(Alog[s]);
    bool geo = true;
#pragma unroll
    for (int s = 0; s < DS; s++)
        geo = geo && (fabsf(A[s] - (float)(s + 1) * A[0]) <= 1e-5f * fabsf(A[s]));

    const float Dd = Dp[d];
    float h[DS];
#pragma unroll
    for (int s = 0; s < DS; s++) h[s] = 0.f;

    const size_t rbase = (size_t)b * L_SEQ;

    constexpr int P = 4;
    float  pf_dt[P], pf_xc[P], pf_z[P];
    float4 pf_BC[P][8];   // B (4x float4) then C (4x float4)

#pragma unroll
    for (int i = 0; i < P; i++) {
        size_t m = rbase + i;
        pf_dt[i] = g_delta[m * DI + d];
        pf_xc[i] = g_xc[m * DI + d];
        pf_z[i]  = g_xz[m * N_XZ + DI + d];
        const float4* BC = (const float4*)(g_dx + m * N_COMB + DI);
#pragma unroll
        for (int q = 0; q < 8; q++) pf_BC[i][q] = BC[q];
    }

    if (geo) {
        const float A0 = A[0];
        for (int l0 = 0; l0 < L_SEQ; l0 += P) {
#pragma unroll
            for (int u = 0; u < P; u++) {
                const int l = l0 + u;
                const float dt  = pf_dt[u];
                const float xcv = pf_xc[u];
                const float zv  = pf_z[u];
                float v[32];
#pragma unroll
                for (int q = 0; q < 8; q++) *(float4*)&v[q * 4] = pf_BC[u][q];
                // prefetch slot u for iteration l+P
                if (l + P < L_SEQ) {
                    size_t m2 = rbase + l + P;
                    pf_dt[u] = g_delta[m2 * DI + d];
                    pf_xc[u] = g_xc[m2 * DI + d];
                    pf_z[u]  = g_xz[m2 * N_XZ + DI + d];
                    const float4* BC2 = (const float4*)(g_dx + m2 * N_COMB + DI);
#pragma unroll
                    for (int q = 0; q < 8; q++) pf_BC[u][q] = BC2[q];
                }
                const float p = __expf(A0 * dt);
                float pw[DS];  // pw[s] = p^(s+1), depth-4 tree
                pw[0] = p;            pw[1]  = p * p;
                pw[2] = pw[1] * p;    pw[3]  = pw[1] * pw[1];
                pw[4] = pw[3] * p;    pw[5]  = pw[3] * pw[1];
                pw[6] = pw[3] * pw[2];pw[7]  = pw[3] * pw[3];
                pw[8] = pw[7] * p;    pw[9]  = pw[7] * pw[1];
                pw[10]= pw[7] * pw[2];pw[11] = pw[7] * pw[3];
                pw[12]= pw[7] * pw[4];pw[13] = pw[7] * pw[5];
                pw[14]= pw[7] * pw[6];pw[15] = pw[7] * pw[7];
                float y0 = 0.f, y1 = 0.f, y2 = 0.f, y3 = 0.f;
#pragma unroll
                for (int s = 0; s < DS; s++) {
                    h[s] = fmaf(pw[s], h[s], dt * v[s]);
                    float t2 = h[s] * v[16 + s];
                    if      ((s & 3) == 0) y0 += t2;
                    else if ((s & 3) == 1) y1 += t2;
                    else if ((s & 3) == 2) y2 += t2;
                    else                   y3 += t2;
                }
                float yv = (y0 + y1) + (y2 + y3);
                float sz = __fdividef(zv, 1.f + __expf(-zv));
                g_y[(rbase + l) * DI + d] = (yv + Dd * xcv) * sz;
            }
        }
    } else {
        // general fallback: per-state exp
        for (int l0 = 0; l0 < L_SEQ; l0 += P) {
#pragma unroll
            for (int u = 0; u < P; u++) {
                const int l = l0 + u;
                const float dt  = pf_dt[u];
                const float xcv = pf_xc[u];
                const float zv  = pf_z[u];
                float v[32];
#pragma unroll
                for (int q = 0; q < 8; q++) *(float4*)&v[q * 4] = pf_BC[u][q];
                if (l + P < L_SEQ) {
                    size_t m2 = rbase + l + P;
                    pf_dt[u] = g_delta[m2 * DI + d];
                    pf_xc[u] = g_xc[m2 * DI + d];
                    pf_z[u]  = g_xz[m2 * N_XZ + DI + d];
                    const float4* BC2 = (const float4*)(g_dx + m2 * N_COMB + DI);
#pragma unroll
                    for (int q = 0; q < 8; q++) pf_BC[u][q] = BC2[q];
                }
                float y0 = 0.f, y1 = 0.f, y2 = 0.f, y3 = 0.f;
#pragma unroll
                for (int s = 0; s < DS; s++) {
                    float dA = __expf(A[s] * dt);
                    h[s] = fmaf(dA, h[s], dt * v[s]);
                    float t2 = h[s] * v[16 + s];
                    if      ((s & 3) == 0) y0 += t2;
                    else if ((s & 3) == 1) y1 += t2;
                    else if ((s & 3) == 2) y2 += t2;
                    else                   y3 += t2;
                }
                float yv = (y0 + y1) + (y2 + y3);
                float sz = __fdividef(zv, 1.f + __expf(-zv));
                g_y[(rbase + l) * DI + d] = (yv + Dd * xcv) * sz;
            }
        }
    }
}

// ---------------- launch ------------------------------------------------
extern "C" void kernel_launch(void* const* d_in, const int* in_sizes, int n_in,
                              void* d_out, int out_size) {
    const float* x      = (const float*)d_in[0];
    const float* W_in   = (const float*)d_in[1];
    const float* W_conv = (const float*)d_in[2];
    const float* W_x    = (const float*)d_in[3];
    const float* W_dt   = (const float*)d_in[4];
    const float* b_dt   = (const float*)d_in[5];
    const float* A_log  = (const float*)d_in[6];
    const float* Dp     = (const float*)d_in[7];
    const float* W_out  = (const float*)d_in[8];
    float* out = (float*)d_out;

    float *xz, *xc, *dx, *yb, *wcomb;
    cudaGetSymbolAddress((void**)&xz,    g_xz);
    cudaGetSymbolAddress((void**)&xc,    g_xc);
    cudaGetSymbolAddress((void**)&dx,    g_dx);
    cudaGetSymbolAddress((void**)&yb,    g_y);
    cudaGetSymbolAddress((void**)&wcomb, g_wcomb);

    // 1) pack combined weight [W_dt ; W_x ; 0]
    pack_w_k<<<(N_COMB * DI + 255) / 256, 256>>>(W_dt, W_x);
    // 2) xz = x @ W_in^T     (4096 x 3072, K=768)
    gemm_nt<<<dim3(N_XZ / BN, M_ROWS / BM), 256>>>(x, W_in, xz, M_ROWS, N_XZ, DM);
    // 3) xc = silu(causal depthwise conv(xz[:, :di]))
    conv_silu_k<<<(M_ROWS * DI + 255) / 256, 256>>>(W_conv);
    // 4) dx = xc @ [W_dt;W_x;0]^T   (4096 x 1664, K=1536)
    gemm_nt<<<dim3(N_COMB / BN, M_ROWS / BM), 256>>>(xc, wcomb, dx, M_ROWS, N_COMB, DI);
    // 5) delta = softplus(dx[:, :di] + b_dt)
    softplus_k<<<(M_ROWS * DI + 255) / 256, 256>>>(b_dt);
    // 6) selective scan + D skip + z gating -> g_y
    scan_k<<<dim3(DI / 32, BATCH), 32>>>(A_log, Dp);
    // 7) out = g_y @ W_out^T  (4096 x 768, K=1536)
    gemm_nt<<<dim3(DM / BN, M_ROWS / BM), 256>>>(yb, W_out, out, M_ROWS, DM, DI);
}

// round 3
// speedup vs baseline: 2.2901x; 2.2901x over previous
#include <cuda_runtime.h>
#include <cuda_bf16.h>
#include <math.h>
#include <stdint.h>

// ---------------- problem sizes ----------------
#define L_SEQ  2048
#define BATCH  2
#define DM     768
#define DI     1536
#define DS     16
#define M_ROWS (BATCH * L_SEQ)   // 4096
#define N_XZ   (2 * DI)          // 3072
#define N_COMB 1664              // 1536 + 32, padded to 13*128
#define CCH    32                // scan chunks
#define CL     64                // chunk length

typedef __nv_bfloat16 bf16;

// ---------------- scratch globals ----------------
__device__ __align__(128) float g_xz[M_ROWS * N_XZ];
__device__ __align__(128) float g_dx[M_ROWS * N_COMB];
__device__ __align__(128) float g_xc[M_ROWS * DI];
__device__ __align__(128) float g_p [M_ROWS * DI];
__device__ __align__(128) float g_yp[M_ROWS * DI];

__device__ __align__(128) bf16 g_xh [M_ROWS * DM],  g_xl [M_ROWS * DM];
__device__ __align__(128) bf16 g_wih[N_XZ * DM],    g_wil[N_XZ * DM];
__device__ __align__(128) bf16 g_wch[N_COMB * DI],  g_wcl[N_COMB * DI];
__device__ __align__(128) bf16 g_xch[M_ROWS * DI],  g_xcl[M_ROWS * DI];
__device__ __align__(128) bf16 g_yh [M_ROWS * DI],  g_yl [M_ROWS * DI];
__device__ __align__(128) bf16 g_woh[DM * DI],      g_wol[DM * DI];

__device__ __align__(128) float g_cdec[BATCH * CCH * DS * DI];
__device__ __align__(128) float g_hend[BATCH * CCH * DS * DI];
__device__ __align__(128) float g_h0  [BATCH * CCH * DS * DI];

// ---------------- PTX helpers (plain sm_80+ PTX only; NO tcgen05) --------
__device__ __forceinline__ uint32_t smem_u32(const void* p) {
    uint32_t a;
    asm("{ .reg .u64 t; cvta.to.shared.u64 t, %1; cvt.u32.u64 %0, t; }" : "=r"(a) : "l"(p));
    return a;
}
#define CP_ASYNC16(dst, src) \
    asm volatile("cp.async.cg.shared.global [%0], [%1], 16;" :: "r"(dst), "l"(src))
#define CP_COMMIT() asm volatile("cp.async.commit_group;")
#define CP_WAIT(n)  asm volatile("cp.async.wait_group %0;" :: "n"(n))
#define LDSM4(r0, r1, r2, r3, a) \
    asm volatile("ldmatrix.sync.aligned.m8n8.x4.shared.b16 {%0,%1,%2,%3}, [%4];" \
                 : "=r"(r0), "=r"(r1), "=r"(r2), "=r"(r3) : "r"(a))
#define MMA16816(c, a, b0, b1) \
    asm volatile("mma.sync.aligned.m16n8k16.row.col.f32.bf16.bf16.f32 " \
                 "{%0,%1,%2,%3}, {%4,%5,%6,%7}, {%8,%9}, {%0,%1,%2,%3};" \
                 : "+f"((c)[0]), "+f"((c)[1]), "+f"((c)[2]), "+f"((c)[3]) \
                 : "r"((a)[0]), "r"((a)[1]), "r"((a)[2]), "r"((a)[3]), \
                   "r"(b0), "r"(b1))

// ---------------- HMMA bf16x3 GEMM: C[M,N] = (Ah+Al)(Bh+Bl)^T ----------------
// 128x128 tile, BK=32; SMEM rows padded to 40 bf16 (80B) for conflict-free
// ldmatrix; 2-stage cp.async pipeline; 3 mma terms: hi*hi + hi*lo + lo*hi.
#define TILE_B   10240            // 128 rows * 80 bytes
#define STAGE_B  (4 * TILE_B)     // Ah, Al, Bh, Bl
#define GSMEM    (2 * STAGE_B)    // 81920

__global__ __launch_bounds__(256, 1)
void gemm_mma(const bf16* __restrict__ Ah, const bf16* __restrict__ Al,
              const bf16* __restrict__ Bh, const bf16* __restrict__ Bl,
              float* __restrict__ C, int M, int N, int K) {
    extern __shared__ __align__(128) char smem[];
    const uint32_t sb = smem_u32(smem);
    const int tid  = threadIdx.x;
    const int lane = tid & 31;
    const int wid  = tid >> 5;
    const int wm   = wid & 3;          // 4 warps in M
    const int wn   = wid >> 2;         // 2 warps in N
    const int bm   = blockIdx.y * 128;
    const int bn   = blockIdx.x * 128;

    const bf16* srcs[4] = { Ah + (size_t)bm * K, Al + (size_t)bm * K,
                            Bh + (size_t)bn * K, Bl + (size_t)bn * K };

    // per-thread load slots: 8 chunks of 16B (2048 chunks/stage)
    int lt_t[8], lt_r[8]; uint32_t lt_o[8];
#pragma unroll
    for (int i = 0; i < 8; i++) {
        int c = i * 256 + tid;
        int t = c >> 9, w = c & 511, r = w >> 2, j = w & 3;
        lt_t[i] = t; lt_r[i] = r;
        lt_o[i] = (uint32_t)(t * TILE_B + r * 80 + j * 16);
    }

    float acc[2][8][4];
#pragma unroll
    for (int mt = 0; mt < 2; mt++)
#pragma unroll
        for (int nt = 0; nt < 8; nt++)
#pragma unroll
            for (int q = 0; q < 4; q++) acc[mt][nt][q] = 0.f;

    // ldmatrix source addresses (within a stage/tile)
    // A: row = lane&15, khalf = lane>>4 (16B units)
    const uint32_t a_off = (uint32_t)((lane & 15) * 80 + (lane >> 4) * 16);
    // B: n = ((lane>>4)<<3) + (lane&7), khalf = (lane>>3)&1
    const uint32_t b_off = (uint32_t)((((lane >> 4) << 3) + (lane & 7)) * 80 +
                                      ((lane >> 3) & 1) * 16);

    const int NC = K >> 5;

    // prologue: stage 0
    {
        const int k0 = 0;
#pragma unroll
        for (int i = 0; i < 8; i++) {
            int c = i * 256 + tid; int j = c & 3;
            CP_ASYNC16(sb + lt_o[i], srcs[lt_t[i]] + (size_t)lt_r[i] * K + k0 + j * 8);
        }
        CP_COMMIT();
    }

    for (int it = 0; it < NC; it++) {
        if (it + 1 < NC) {
            const uint32_t stb = sb + ((it + 1) & 1) * STAGE_B;
            const int k0 = (it + 1) << 5;
#pragma unroll
            for (int i = 0; i < 8; i++) {
                int c = i * 256 + tid; int j = c & 3;
                CP_ASYNC16(stb + lt_o[i], srcs[lt_t[i]] + (size_t)lt_r[i] * K + k0 + j * 8);
            }
            CP_COMMIT();
            CP_WAIT(1);
        } else {
            CP_WAIT(0);
        }
        __syncthreads();

        const uint32_t st = sb + (it & 1) * STAGE_B;
        const uint32_t aHb = st + 0 * TILE_B + wm * 32 * 80 + a_off;
        const uint32_t aLb = st + 1 * TILE_B + wm * 32 * 80 + a_off;
        const uint32_t bHb = st + 2 * TILE_B + wn * 64 * 80 + b_off;
        const uint32_t bLb = st + 3 * TILE_B + wn * 64 * 80 + b_off;

#pragma unroll
        for (int kk = 0; kk < 2; kk++) {
            const uint32_t ko = kk * 32;
            uint32_t ah[2][4], al[2][4];
#pragma unroll
            for (int mt = 0; mt < 2; mt++) {
                LDSM4(ah[mt][0], ah[mt][1], ah[mt][2], ah[mt][3],
                      aHb + mt * 16 * 80 + ko);
                LDSM4(al[mt][0], al[mt][1], al[mt][2], al[mt][3],
                      aLb + mt * 16 * 80 + ko);
            }
            uint32_t bh[4][4], bl[4][4];
#pragma unroll
            for (int bt = 0; bt < 4; bt++) {
                LDSM4(bh[bt][0], bh[bt][1], bh[bt][2], bh[bt][3],
                      bHb + bt * 16 * 80 + ko);
                LDSM4(bl[bt][0], bl[bt][1], bl[bt][2], bl[bt][3],
                      bLb + bt * 16 * 80 + ko);
            }
#pragma unroll
            for (int mt = 0; mt < 2; mt++)
#pragma unroll
                for (int nt = 0; nt < 8; nt++) {
                    const int bt = nt >> 1, hh = (nt & 1) << 1;
                    MMA16816(acc[mt][nt], ah[mt], bh[bt][hh], bh[bt][hh + 1]);
                    MMA16816(acc[mt][nt], ah[mt], bl[bt][hh], bl[bt][hh + 1]);
                    MMA16816(acc[mt][nt], al[mt], bh[bt][hh], bh[bt][hh + 1]);
                }
        }
        __syncthreads();
    }

    // epilogue: direct fp32 stores (c frag: rows lane>>2 / +8, cols (lane&3)*2)
    const int r0 = bm + wm * 32 + (lane >> 2);
    const int c0 = bn + wn * 64 + (lane & 3) * 2;
#pragma unroll
    for (int mt = 0; mt < 2; mt++)
#pragma unroll
        for (int nt = 0; nt < 8; nt++) {
            float* p0 = C + (size_t)(r0 + mt * 16) * N + c0 + nt * 8;
            *(float2*)p0                  = make_float2(acc[mt][nt][0], acc[mt][nt][1]);
            *(float2*)(p0 + (size_t)8 * N) = make_float2(acc[mt][nt][2], acc[mt][nt][3]);
        }
}

// ---------------- fp32 -> bf16 hi/lo split ----------------
__device__ __forceinline__ void split_bf16(float v, bf16& h, bf16& l) {
    h = __float2bfloat16_rn(v);
    l = __float2bfloat16_rn(v - __bfloat162float(h));
}
__global__ void cvt_split_k(const float* __restrict__ s, bf16* __restrict__ h,
                            bf16* __restrict__ l, int n) {
    int i = blockIdx.x * 256 + threadIdx.x;
    if (i < n) split_bf16(s[i], h[i], l[i]);
}
__global__ void pack_w_k(const float* __restrict__ Wdt, const float* __restrict__ Wx) {
    int idx = blockIdx.x * 256 + threadIdx.x;
    if (idx >= N_COMB * DI) return;
    int row = idx / DI, col = idx - row * DI;
    float v = 0.f;
    if (row < DI)           v = Wdt[idx];
    else if (row < DI + 32) v = Wx[(row - DI) * DI + col];
    split_bf16(v, g_wch[idx], g_wcl[idx]);
}

// ---------------- conv + SiLU (fp32 + bf16 split outputs) ----------------
__global__ void conv_silu_k(const float* __restrict__ Wc) {
    int idx = blockIdx.x * 256 + threadIdx.x;
    if (idx >= M_ROWS * DI) return;
    int d = idx % DI, m = idx / DI, l = m & (L_SEQ - 1);
    float w0 = Wc[d*4+0], w1 = Wc[d*4+1], w2 = Wc[d*4+2], w3 = Wc[d*4+3];
    float s = g_xz[(size_t)m * N_XZ + d] * w3;
    if (l >= 1) s = fmaf(g_xz[(size_t)(m-1) * N_XZ + d], w2, s);
    if (l >= 2) s = fmaf(g_xz[(size_t)(m-2) * N_XZ + d], w1, s);
    if (l >= 3) s = fmaf(g_xz[(size_t)(m-3) * N_XZ + d], w0, s);
    float v = __fdividef(s, 1.f + __expf(-s));
    g_xc[idx] = v;
    split_bf16(v, g_xch[idx], g_xcl[idx]);
}

// ---------------- scan helpers ----------------
__device__ __forceinline__ void pow16(float p, float* pw) {
    pw[0]=p;          pw[1]=p*p;        pw[2]=pw[1]*p;     pw[3]=pw[1]*pw[1];
    pw[4]=pw[3]*p;    pw[5]=pw[3]*pw[1];pw[6]=pw[3]*pw[2]; pw[7]=pw[3]*pw[3];
    pw[8]=pw[7]*p;    pw[9]=pw[7]*pw[1];pw[10]=pw[7]*pw[2];pw[11]=pw[7]*pw[3];
    pw[12]=pw[7]*pw[4];pw[13]=pw[7]*pw[5];pw[14]=pw[7]*pw[6];pw[15]=pw[7]*pw[7];
}
__device__ __forceinline__ bool geo_check(const float* Alog, float* A) {
#pragma unroll
    for (int s = 0; s < DS; s++) A[s] = -__expf(Alog[s]);
    bool geo = true;
#pragma unroll
    for (int s = 0; s < DS; s++)
        geo = geo && (fabsf(A[s] - (float)(s + 1) * A[0]) <= 1e-5f * fabsf(A[s]));
    return geo;
}
__device__ __forceinline__ float softplus_f(float x) {
    return (x > 20.f) ? x : log1pf(__expf(x));
}

// ---------------- scan phase A: local scans ----------------
__global__ __launch_bounds__(128)
void scan_a(const float* __restrict__ Alog, const float* __restrict__ bdt) {
    __shared__ float sBC[CL * 32];
    const int d = blockIdx.x * 128 + threadIdx.x;
    const int c = blockIdx.y, b = blockIdx.z;
    const int m0 = b * L_SEQ + c * CL;
    for (int e = threadIdx.x; e < CL * 32; e += 128) {
        int l = e >> 5, q = e & 31;
        sBC[e] = g_dx[(size_t)(m0 + l) * N_COMB + DI + q];
    }
    __syncthreads();

    float A[DS];
    const bool geo = geo_check(Alog, A);
    const float bd = bdt[d];
    float h[DS];
#pragma unroll
    for (int s = 0; s < DS; s++) h[s] = 0.f;
    const size_t base = ((size_t)(b * CCH + c) * DS) * DI + d;

    if (geo) {
        const float A0 = A[0];
        float pp = 1.f;
        for (int l = 0; l < CL; l++) {
            const size_t m = m0 + l;
            float dt = softplus_f(g_dx[m * N_COMB + d] + bd);
            float p = __expf(A0 * dt);
            g_p[m * DI + d] = p;
            pp *= p;
            float pw[DS]; pow16(p, pw);
            float y0=0.f, y1=0.f, y2=0.f, y3=0.f;
#pragma unroll
            for (int s = 0; s < DS; s++) {
                h[s] = fmaf(pw[s], h[s], dt * sBC[l * 32 + s]);
                float t = h[s] * sBC[l * 32 + 16 + s];
                if ((s&3)==0) y0+=t; else if ((s&3)==1) y1+=t;
                else if ((s&3)==2) y2+=t; else y3+=t;
            }
            g_yp[m * DI + d] = (y0 + y1) + (y2 + y3);
        }
        float dw[DS]; pow16(pp, dw);
#pragma unroll
        for (int s = 0; s < DS; s++) {
            g_cdec[base + (size_t)s * DI] = dw[s];
            g_hend[base + (size_t)s * DI] = h[s];
        }
    } else {
        float dec[DS];
#pragma unroll
        for (int s = 0; s < DS; s++) dec[s] = 1.f;
        for (int l = 0; l < CL; l++) {
            const size_t m = m0 + l;
            float dt = softplus_f(g_dx[m * N_COMB + d] + bd);
            float y0=0.f, y1=0.f, y2=0.f, y3=0.f;
#pragma unroll
            for (int s = 0; s < DS; s++) {
                float dA = __expf(A[s] * dt);
                dec[s] *= dA;
                h[s] = fmaf(dA, h[s], dt * sBC[l * 32 + s]);
                float t = h[s] * sBC[l * 32 + 16 + s];
                if ((s&3)==0) y0+=t; else if ((s&3)==1) y1+=t;
                else if ((s&3)==2) y2+=t; else y3+=t;
            }
            g_yp[m * DI + d] = (y0 + y1) + (y2 + y3);
        }
#pragma unroll
        for (int s = 0; s < DS; s++) {
            g_cdec[base + (size_t)s * DI] = dec[s];
            g_hend[base + (size_t)s * DI] = h[s];
        }
    }
}

// ---------------- scan phase B: chunk combine ----------------
__global__ __launch_bounds__(128)
void scan_b() {
    const int d = blockIdx.x * 128 + threadIdx.x;
    const int b = blockIdx.y;
    float H[DS];
#pragma unroll
    for (int s = 0; s < DS; s++) H[s] = 0.f;
    for (int c = 0; c < CCH; c++) {
        const size_t base = ((size_t)(b * CCH + c) * DS) * DI + d;
#pragma unroll
        for (int s = 0; s < DS; s++) {
            g_h0[base + (size_t)s * DI] = H[s];
            H[s] = fmaf(g_cdec[base + (size_t)s * DI], H[s],
                        g_hend[base + (size_t)s * DI]);
        }
    }
}

// ---------------- scan phase C: correction + gate + bf16 split ----------------
__global__ __launch_bounds__(128)
void scan_c(const float* __restrict__ Alog, const float* __restrict__ Dp,
            const float* __restrict__ bdt) {
    __shared__ float sC[CL * 16];
    const int d = blockIdx.x * 128 + threadIdx.x;
    const int c = blockIdx.y, b = blockIdx.z;
    const int m0 = b * L_SEQ + c * CL;
    for (int e = threadIdx.x; e < CL * 16; e += 128) {
        int l = e >> 4, q = e & 15;
        sC[e] = g_dx[(size_t)(m0 + l) * N_COMB + DI + 16 + q];
    }
    __syncthreads();

    float A[DS];
    const bool geo = geo_check(Alog, A);
    const float Dd = Dp[d];
    const float bd = bdt[d];
    float H0[DS];
    const size_t base = ((size_t)(b * CCH + c) * DS) * DI + d;
#pragma unroll
    for (int s = 0; s < DS; s++) H0[s] = g_h0[base + (size_t)s * DI];

    if (geo) {
        float run = 1.f;
        for (int l = 0; l < CL; l++) {
            const size_t m = m0 + l;
            run *= g_p[m * DI + d];
            float rw[DS]; pow16(run, rw);
            float corr = 0.f;
#pragma unroll
            for (int s = 0; s < DS; s++)
                corr = fmaf(rw[s] * H0[s], sC[l * 16 + s], corr);
            float y = g_yp[m * DI + d] + corr;
            float z = g_xz[m * N_XZ + DI + d];
            float o = (y + Dd * g_xc[m * DI + d]) *
                      __fdividef(z, 1.f + __expf(-z));
            split_bf16(o, g_yh[m * DI + d], g_yl[m * DI + d]);
        }
    } else {
        float run[DS];
#pragma unroll
        for (int s = 0; s < DS; s++) run[s] = 1.f;
        for (int l = 0; l < CL; l++) {
            const size_t m = m0 + l;
            float dt = softplus_f(g_dx[m * N_COMB + d] + bd);
            float corr = 0.f;
#pragma unroll
            for (int s = 0; s < DS; s++) {
                run[s] *= __expf(A[s] * dt);
                corr = fmaf(run[s] * H0[s], sC[l * 16 + s], corr);
            }
            float y = g_yp[m * DI + d] + corr;
            float z = g_xz[m * N_XZ + DI + d];
            float o = (y + Dd * g_xc[m * DI + d]) *
                      __fdividef(z, 1.f + __expf(-z));
            split_bf16(o, g_yh[m * DI + d], g_yl[m * DI + d]);
        }
    }
}

// ---------------- launch ----------------
extern "C" void kernel_launch(void* const* d_in, const int* in_sizes, int n_in,
                              void* d_out, int out_size) {
    const float* x      = (const float*)d_in[0];
    const float* W_in   = (const float*)d_in[1];
    const float* W_conv = (const float*)d_in[2];
    const float* W_x    = (const float*)d_in[3];
    const float* W_dt   = (const float*)d_in[4];
    const float* b_dt   = (const float*)d_in[5];
    const float* A_log  = (const float*)d_in[6];
    const float* Dp     = (const float*)d_in[7];
    const float* W_out  = (const float*)d_in[8];
    float* out = (float*)d_out;

    cudaFuncSetAttribute(gemm_mma, cudaFuncAttributeMaxDynamicSharedMemorySize,
                         GSMEM);

    float *xz, *dx;
    bf16 *xh, *xl, *wih, *wil, *wch, *wcl, *xch, *xcl, *yh, *yl, *woh, *wol;
    cudaGetSymbolAddress((void**)&xz,  g_xz);
    cudaGetSymbolAddress((void**)&dx,  g_dx);
    cudaGetSymbolAddress((void**)&xh,  g_xh);  cudaGetSymbolAddress((void**)&xl,  g_xl);
    cudaGetSymbolAddress((void**)&wih, g_wih); cudaGetSymbolAddress((void**)&wil, g_wil);
    cudaGetSymbolAddress((void**)&wch, g_wch); cudaGetSymbolAddress((void**)&wcl, g_wcl);
    cudaGetSymbolAddress((void**)&xch, g_xch); cudaGetSymbolAddress((void**)&xcl, g_xcl);
    cudaGetSymbolAddress((void**)&yh,  g_yh);  cudaGetSymbolAddress((void**)&yl,  g_yl);
    cudaGetSymbolAddress((void**)&woh, g_woh); cudaGetSymbolAddress((void**)&wol, g_wol);

    cvt_split_k<<<(M_ROWS*DM + 255)/256, 256>>>(x, xh, xl, M_ROWS*DM);
    cvt_split_k<<<(N_XZ*DM + 255)/256, 256>>>(W_in, wih, wil, N_XZ*DM);
    cvt_split_k<<<(DM*DI + 255)/256, 256>>>(W_out, woh, wol, DM*DI);
    pack_w_k<<<(N_COMB*DI + 255)/256, 256>>>(W_dt, W_x);

    // xz = x @ W_in^T
    gemm_mma<<<dim3(N_XZ/128, M_ROWS/128), 256, GSMEM>>>(
        xh, xl, wih, wil, xz, M_ROWS, N_XZ, DM);
    // xc = silu(conv(xz[:, :di]))
    conv_silu_k<<<(M_ROWS*DI + 255)/256, 256>>>(W_conv);
    // dx = xc @ [W_dt;W_x;0]^T
    gemm_mma<<<dim3(N_COMB/128, M_ROWS/128), 256, GSMEM>>>(
        xch, xcl, wch, wcl, dx, M_ROWS, N_COMB, DI);
    // chunked selective scan
    scan_a<<<dim3(DI/128, CCH, BATCH), 128>>>(A_log, b_dt);
    scan_b<<<dim3(DI/128, BATCH), 128>>>();
    scan_c<<<dim3(DI/128, CCH, BATCH), 128>>>(A_log, Dp, b_dt);
    // out = y @ W_out^T
    gemm_mma<<<dim3(DM/128, M_ROWS/128), 256, GSMEM>>>(
        yh, yl, woh, wol, out, M_ROWS, DM, DI);
}

// round 4
// speedup vs baseline: 2.5890x; 1.1305x over previous
#include <cuda_runtime.h>
#include <cuda_bf16.h>
#include <math.h>
#include <stdint.h>

// ---------------- problem sizes ----------------
#define L_SEQ  2048
#define BATCH  2
#define DM     768
#define DI     1536
#define DS     16
#define M_ROWS (BATCH * L_SEQ)   // 4096
#define N_XZ   (2 * DI)          // 3072
#define N_COMB 1664              // 1536 + 32, padded to 13*128
#define CCH    32                // scan chunks
#define CL     64                // chunk length

typedef __nv_bfloat16 bf16;

// ---------------- scratch globals ----------------
__device__ __align__(128) float g_xz[M_ROWS * N_XZ];
__device__ __align__(128) float g_dx[M_ROWS * N_COMB];
__device__ __align__(128) float g_xc[M_ROWS * DI];
__device__ __align__(128) float g_p [M_ROWS * DI];
__device__ __align__(128) float g_yp[M_ROWS * DI];

__device__ __align__(128) bf16 g_xh [M_ROWS * DM],  g_xl [M_ROWS * DM];
__device__ __align__(128) bf16 g_wih[N_XZ * DM],    g_wil[N_XZ * DM];
__device__ __align__(128) bf16 g_wch[N_COMB * DI],  g_wcl[N_COMB * DI];
__device__ __align__(128) bf16 g_xch[M_ROWS * DI],  g_xcl[M_ROWS * DI];
__device__ __align__(128) bf16 g_yh [M_ROWS * DI],  g_yl [M_ROWS * DI];
__device__ __align__(128) bf16 g_woh[DM * DI],      g_wol[DM * DI];

__device__ __align__(128) float g_cdec[BATCH * CCH * DS * DI];
__device__ __align__(128) float g_hend[BATCH * CCH * DS * DI];
__device__ __align__(128) float g_h0  [BATCH * CCH * DS * DI];

// ---------------- PTX helpers (plain sm_80+ PTX; NO tcgen05) --------
__device__ __forceinline__ uint32_t smem_u32(const void* p) {
    uint32_t a;
    asm("{ .reg .u64 t; cvta.to.shared.u64 t, %1; cvt.u32.u64 %0, t; }" : "=r"(a) : "l"(p));
    return a;
}
#define CP_ASYNC16(dst, src) \
    asm volatile("cp.async.cg.shared.global [%0], [%1], 16;" :: "r"(dst), "l"(src))
#define CP_COMMIT() asm volatile("cp.async.commit_group;")
#define CP_WAIT(n)  asm volatile("cp.async.wait_group %0;" :: "n"(n))
#define LDSM4(r0, r1, r2, r3, a) \
    asm volatile("ldmatrix.sync.aligned.m8n8.x4.shared.b16 {%0,%1,%2,%3}, [%4];" \
                 : "=r"(r0), "=r"(r1), "=r"(r2), "=r"(r3) : "r"(a))
#define MMA16816(c, a, b0, b1) \
    asm volatile("mma.sync.aligned.m16n8k16.row.col.f32.bf16.bf16.f32 " \
                 "{%0,%1,%2,%3}, {%4,%5,%6,%7}, {%8,%9}, {%0,%1,%2,%3};" \
                 : "+f"((c)[0]), "+f"((c)[1]), "+f"((c)[2]), "+f"((c)[3]) \
                 : "r"((a)[0]), "r"((a)[1]), "r"((a)[2]), "r"((a)[3]), \
                   "r"(b0), "r"(b1))

// ---------------- HMMA bf16x3 GEMM: C[M,N] = (Ah+Al)(Bh+Bl)^T ----------------
// 128x128 tile, BK=32; SMEM rows padded to 40 bf16 (80B); 2-stage cp.async;
// 3 mma terms: hi*hi + hi*lo + lo*hi. 2 CTAs/SM (128-reg cap) for overlap.
#define TILE_B   10240            // 128 rows * 80 bytes
#define STAGE_B  (4 * TILE_B)     // Ah, Al, Bh, Bl
#define GSMEM    (2 * STAGE_B)    // 81920

__global__ __launch_bounds__(256, 2)
void gemm_mma(const bf16* __restrict__ Ah, const bf16* __restrict__ Al,
              const bf16* __restrict__ Bh, const bf16* __restrict__ Bl,
              float* __restrict__ C, int M, int N, int K) {
    extern __shared__ __align__(128) char smem[];
    const uint32_t sb = smem_u32(smem);
    const int tid  = threadIdx.x;
    const int lane = tid & 31;
    const int wid  = tid >> 5;
    const int wm   = wid & 3;          // 4 warps in M
    const int wn   = wid >> 2;         // 2 warps in N
    const int bm   = blockIdx.y * 128;
    const int bn   = blockIdx.x * 128;

    const bf16* srcs[4] = { Ah + (size_t)bm * K, Al + (size_t)bm * K,
                            Bh + (size_t)bn * K, Bl + (size_t)bn * K };

    // per-thread load slots: 8 chunks of 16B (2048 chunks/stage)
    int lt_t[8], lt_r[8]; uint32_t lt_o[8];
#pragma unroll
    for (int i = 0; i < 8; i++) {
        int c = i * 256 + tid;
        int t = c >> 9, w = c & 511, r = w >> 2, j = w & 3;
        lt_t[i] = t; lt_r[i] = r;
        lt_o[i] = (uint32_t)(t * TILE_B + r * 80 + j * 16);
    }

    float acc[2][8][4];
#pragma unroll
    for (int mt = 0; mt < 2; mt++)
#pragma unroll
        for (int nt = 0; nt < 8; nt++)
#pragma unroll
            for (int q = 0; q < 4; q++) acc[mt][nt][q] = 0.f;

    // ldmatrix source addresses (within a stage/tile)
    const uint32_t a_off = (uint32_t)((lane & 15) * 80 + (lane >> 4) * 16);
    const uint32_t b_off = (uint32_t)((((lane >> 4) << 3) + (lane & 7)) * 80 +
                                      ((lane >> 3) & 1) * 16);

    const int NC = K >> 5;

    // prologue: stage 0
    {
#pragma unroll
        for (int i = 0; i < 8; i++) {
            int c = i * 256 + tid; int j = c & 3;
            CP_ASYNC16(sb + lt_o[i], srcs[lt_t[i]] + (size_t)lt_r[i] * K + j * 8);
        }
        CP_COMMIT();
    }

    for (int it = 0; it < NC; it++) {
        if (it + 1 < NC) {
            const uint32_t stb = sb + ((it + 1) & 1) * STAGE_B;
            const int k0 = (it + 1) << 5;
#pragma unroll
            for (int i = 0; i < 8; i++) {
                int c = i * 256 + tid; int j = c & 3;
                CP_ASYNC16(stb + lt_o[i], srcs[lt_t[i]] + (size_t)lt_r[i] * K + k0 + j * 8);
            }
            CP_COMMIT();
            CP_WAIT(1);
        } else {
            CP_WAIT(0);
        }
        __syncthreads();

        const uint32_t st = sb + (it & 1) * STAGE_B;
        const uint32_t aHb = st + 0 * TILE_B + wm * 32 * 80 + a_off;
        const uint32_t aLb = st + 1 * TILE_B + wm * 32 * 80 + a_off;
        const uint32_t bHb = st + 2 * TILE_B + wn * 64 * 80 + b_off;
        const uint32_t bLb = st + 3 * TILE_B + wn * 64 * 80 + b_off;

#pragma unroll
        for (int kk = 0; kk < 2; kk++) {
            const uint32_t ko = kk * 32;
            uint32_t ah[2][4], al[2][4];
#pragma unroll
            for (int mt = 0; mt < 2; mt++) {
                LDSM4(ah[mt][0], ah[mt][1], ah[mt][2], ah[mt][3],
                      aHb + mt * 16 * 80 + ko);
                LDSM4(al[mt][0], al[mt][1], al[mt][2], al[mt][3],
                      aLb + mt * 16 * 80 + ko);
            }
            // process B tiles in two halves to keep register count <= 128
#pragma unroll
            for (int half = 0; half < 2; half++) {
                uint32_t bh[2][4], bl[2][4];
#pragma unroll
                for (int u = 0; u < 2; u++) {
                    const int bt = half * 2 + u;
                    LDSM4(bh[u][0], bh[u][1], bh[u][2], bh[u][3],
                          bHb + bt * 16 * 80 + ko);
                    LDSM4(bl[u][0], bl[u][1], bl[u][2], bl[u][3],
                          bLb + bt * 16 * 80 + ko);
                }
#pragma unroll
                for (int mt = 0; mt < 2; mt++)
#pragma unroll
                    for (int v = 0; v < 4; v++) {
                        const int nt = half * 4 + v;
                        const int u = v >> 1, hh = (v & 1) << 1;
                        MMA16816(acc[mt][nt], ah[mt], bh[u][hh], bh[u][hh + 1]);
                        MMA16816(acc[mt][nt], ah[mt], bl[u][hh], bl[u][hh + 1]);
                        MMA16816(acc[mt][nt], al[mt], bh[u][hh], bh[u][hh + 1]);
                    }
            }
        }
        __syncthreads();
    }

    // epilogue: direct fp32 stores
    const int r0 = bm + wm * 32 + (lane >> 2);
    const int c0 = bn + wn * 64 + (lane & 3) * 2;
#pragma unroll
    for (int mt = 0; mt < 2; mt++)
#pragma unroll
        for (int nt = 0; nt < 8; nt++) {
            float* p0 = C + (size_t)(r0 + mt * 16) * N + c0 + nt * 8;
            *(float2*)p0                   = make_float2(acc[mt][nt][0], acc[mt][nt][1]);
            *(float2*)(p0 + (size_t)8 * N) = make_float2(acc[mt][nt][2], acc[mt][nt][3]);
        }
}

// ---------------- fp32 -> bf16 hi/lo split ----------------
__device__ __forceinline__ void split_bf16(float v, bf16& h, bf16& l) {
    h = __float2bfloat16_rn(v);
    l = __float2bfloat16_rn(v - __bfloat162float(h));
}

// fused prep: split x, W_in, W_out; pack+split [W_dt;W_x;0]
#define N_JOB0 (M_ROWS * DM)
#define N_JOB1 (N_XZ * DM)
#define N_JOB2 (DM * DI)
#define N_JOB3 (N_COMB * DI)
__global__ void prep_k(const float* __restrict__ x, const float* __restrict__ Win,
                       const float* __restrict__ Wout,
                       const float* __restrict__ Wdt, const float* __restrict__ Wx) {
    int idx = blockIdx.x * 256 + threadIdx.x;
    if (idx < N_JOB0) {
        split_bf16(x[idx], g_xh[idx], g_xl[idx]);
        return;
    }
    idx -= N_JOB0;
    if (idx < N_JOB1) {
        split_bf16(Win[idx], g_wih[idx], g_wil[idx]);
        return;
    }
    idx -= N_JOB1;
    if (idx < N_JOB2) {
        split_bf16(Wout[idx], g_woh[idx], g_wol[idx]);
        return;
    }
    idx -= N_JOB2;
    if (idx < N_JOB3) {
        int row = idx / DI, col = idx - row * DI;
        float v = 0.f;
        if (row < DI)           v = Wdt[idx];
        else if (row < DI + 32) v = Wx[(row - DI) * DI + col];
        split_bf16(v, g_wch[idx], g_wcl[idx]);
    }
}
#define N_PREP (N_JOB0 + N_JOB1 + N_JOB2 + N_JOB3)

// ---------------- conv + SiLU (fp32 + bf16 split outputs) ----------------
__global__ void conv_silu_k(const float* __restrict__ Wc) {
    int idx = blockIdx.x * 256 + threadIdx.x;
    if (idx >= M_ROWS * DI) return;
    int d = idx % DI, m = idx / DI, l = m & (L_SEQ - 1);
    float w0 = Wc[d*4+0], w1 = Wc[d*4+1], w2 = Wc[d*4+2], w3 = Wc[d*4+3];
    float s = g_xz[(size_t)m * N_XZ + d] * w3;
    if (l >= 1) s = fmaf(g_xz[(size_t)(m-1) * N_XZ + d], w2, s);
    if (l >= 2) s = fmaf(g_xz[(size_t)(m-2) * N_XZ + d], w1, s);
    if (l >= 3) s = fmaf(g_xz[(size_t)(m-3) * N_XZ + d], w0, s);
    float v = __fdividef(s, 1.f + __expf(-s));
    g_xc[idx] = v;
    split_bf16(v, g_xch[idx], g_xcl[idx]);
}

// ---------------- scan helpers ----------------
__device__ __forceinline__ void pow16(float p, float* pw) {
    pw[0]=p;          pw[1]=p*p;        pw[2]=pw[1]*p;     pw[3]=pw[1]*pw[1];
    pw[4]=pw[3]*p;    pw[5]=pw[3]*pw[1];pw[6]=pw[3]*pw[2]; pw[7]=pw[3]*pw[3];
    pw[8]=pw[7]*p;    pw[9]=pw[7]*pw[1];pw[10]=pw[7]*pw[2];pw[11]=pw[7]*pw[3];
    pw[12]=pw[7]*pw[4];pw[13]=pw[7]*pw[5];pw[14]=pw[7]*pw[6];pw[15]=pw[7]*pw[7];
}
__device__ __forceinline__ bool geo_check(const float* Alog, float* A) {
#pragma unroll
    for (int s = 0; s < DS; s++) A[s] = -__expf(Alog[s]);
    bool geo = true;
#pragma unroll
    for (int s = 0; s < DS; s++)
        geo = geo && (fabsf(A[s] - (float)(s + 1) * A[0]) <= 1e-5f * fabsf(A[s]));
    return geo;
}
__device__ __forceinline__ float softplus_f(float x) {
    return (x > 20.f) ? x : log1pf(__expf(x));
}

// ---------------- scan phase A: local scans ----------------
__global__ __launch_bounds__(128)
void scan_a(const float* __restrict__ Alog, const float* __restrict__ bdt) {
    __shared__ float sBC[CL * 32];
    const int d = blockIdx.x * 128 + threadIdx.x;
    const int c = blockIdx.y, b = blockIdx.z;
    const int m0 = b * L_SEQ + c * CL;
    for (int e = threadIdx.x; e < CL * 32; e += 128) {
        int l = e >> 5, q = e & 31;
        sBC[e] = g_dx[(size_t)(m0 + l) * N_COMB + DI + q];
    }
    __syncthreads();

    float A[DS];
    const bool geo = geo_check(Alog, A);
    const float bd = bdt[d];
    float h[DS];
#pragma unroll
    for (int s = 0; s < DS; s++) h[s] = 0.f;
    const size_t base = ((size_t)(b * CCH + c) * DS) * DI + d;

    if (geo) {
        const float A0 = A[0];
        float pp = 1.f;
        for (int l = 0; l < CL; l++) {
            const size_t m = m0 + l;
            float dt = softplus_f(g_dx[m * N_COMB + d] + bd);
            float p = __expf(A0 * dt);
            g_p[m * DI + d] = p;
            pp *= p;
            float pw[DS]; pow16(p, pw);
            float y0=0.f, y1=0.f, y2=0.f, y3=0.f;
#pragma unroll
            for (int s = 0; s < DS; s++) {
                h[s] = fmaf(pw[s], h[s], dt * sBC[l * 32 + s]);
                float t = h[s] * sBC[l * 32 + 16 + s];
                if ((s&3)==0) y0+=t; else if ((s&3)==1) y1+=t;
                else if ((s&3)==2) y2+=t; else y3+=t;
            }
            g_yp[m * DI + d] = (y0 + y1) + (y2 + y3);
        }
        float dw[DS]; pow16(pp, dw);
#pragma unroll
        for (int s = 0; s < DS; s++) {
            g_cdec[base + (size_t)s * DI] = dw[s];
            g_hend[base + (size_t)s * DI] = h[s];
        }
    } else {
        float dec[DS];
#pragma unroll
        for (int s = 0; s < DS; s++) dec[s] = 1.f;
        for (int l = 0; l < CL; l++) {
            const size_t m = m0 + l;
            float dt = softplus_f(g_dx[m * N_COMB + d] + bd);
            float y0=0.f, y1=0.f, y2=0.f, y3=0.f;
#pragma unroll
            for (int s = 0; s < DS; s++) {
                float dA = __expf(A[s] * dt);
                dec[s] *= dA;
                h[s] = fmaf(dA, h[s], dt * sBC[l * 32 + s]);
                float t = h[s] * sBC[l * 32 + 16 + s];
                if ((s&3)==0) y0+=t; else if ((s&3)==1) y1+=t;
                else if ((s&3)==2) y2+=t; else y3+=t;
            }
            g_yp[m * DI + d] = (y0 + y1) + (y2 + y3);
        }
#pragma unroll
        for (int s = 0; s < DS; s++) {
            g_cdec[base + (size_t)s * DI] = dec[s];
            g_hend[base + (size_t)s * DI] = h[s];
        }
    }
}

// ---------------- scan phase B: chunk combine ----------------
__global__ __launch_bounds__(128)
void scan_b() {
    const int d = blockIdx.x * 128 + threadIdx.x;
    const int b = blockIdx.y;
    float H[DS];
#pragma unroll
    for (int s = 0; s < DS; s++) H[s] = 0.f;
    for (int c = 0; c < CCH; c++) {
        const size_t base = ((size_t)(b * CCH + c) * DS) * DI + d;
#pragma unroll
        for (int s = 0; s < DS; s++) {
            g_h0[base + (size_t)s * DI] = H[s];
            H[s] = fmaf(g_cdec[base + (size_t)s * DI], H[s],
                        g_hend[base + (size_t)s * DI]);
        }
    }
}

// ---------------- scan phase C: correction + gate + bf16 split ----------------
__global__ __launch_bounds__(128)
void scan_c(const float* __restrict__ Alog, const float* __restrict__ Dp,
            const float* __restrict__ bdt) {
    __shared__ float sC[CL * 16];
    const int d = blockIdx.x * 128 + threadIdx.x;
    const int c = blockIdx.y, b = blockIdx.z;
    const int m0 = b * L_SEQ + c * CL;
    for (int e = threadIdx.x; e < CL * 16; e += 128) {
        int l = e >> 4, q = e & 15;
        sC[e] = g_dx[(size_t)(m0 + l) * N_COMB + DI + 16 + q];
    }
    __syncthreads();

    float A[DS];
    const bool geo = geo_check(Alog, A);
    const float Dd = Dp[d];
    const float bd = bdt[d];
    float H0[DS];
    const size_t base = ((size_t)(b * CCH + c) * DS) * DI + d;
#pragma unroll
    for (int s = 0; s < DS; s++) H0[s] = g_h0[base + (size_t)s * DI];

    if (geo) {
        float run = 1.f;
        for (int l = 0; l < CL; l++) {
            const size_t m = m0 + l;
            run *= g_p[m * DI + d];
            float rw[DS]; pow16(run, rw);
            float corr = 0.f;
#pragma unroll
            for (int s = 0; s < DS; s++)
                corr = fmaf(rw[s] * H0[s], sC[l * 16 + s], corr);
            float y = g_yp[m * DI + d] + corr;
            float z = g_xz[m * N_XZ + DI + d];
            float o = (y + Dd * g_xc[m * DI + d]) *
                      __fdividef(z, 1.f + __expf(-z));
            split_bf16(o, g_yh[m * DI + d], g_yl[m * DI + d]);
        }
    } else {
        float run[DS];
#pragma unroll
        for (int s = 0; s < DS; s++) run[s] = 1.f;
        for (int l = 0; l < CL; l++) {
            const size_t m = m0 + l;
            float dt = softplus_f(g_dx[m * N_COMB + d] + bd);
            float corr = 0.f;
#pragma unroll
            for (int s = 0; s < DS; s++) {
                run[s] *= __expf(A[s] * dt);
                corr = fmaf(run[s] * H0[s], sC[l * 16 + s], corr);
            }
            float y = g_yp[m * DI + d] + corr;
            float z = g_xz[m * N_XZ + DI + d];
            float o = (y + Dd * g_xc[m * DI + d]) *
                      __fdividef(z, 1.f + __expf(-z));
            split_bf16(o, g_yh[m * DI + d], g_yl[m * DI + d]);
        }
    }
}

// ---------------- launch ----------------
extern "C" void kernel_launch(void* const* d_in, const int* in_sizes, int n_in,
                              void* d_out, int out_size) {
    const float* x      = (const float*)d_in[0];
    const float* W_in   = (const float*)d_in[1];
    const float* W_conv = (const float*)d_in[2];
    const float* W_x    = (const float*)d_in[3];
    const float* W_dt   = (const float*)d_in[4];
    const float* b_dt   = (const float*)d_in[5];
    const float* A_log  = (const float*)d_in[6];
    const float* Dp     = (const float*)d_in[7];
    const float* W_out  = (const float*)d_in[8];
    float* out = (float*)d_out;

    cudaFuncSetAttribute(gemm_mma, cudaFuncAttributeMaxDynamicSharedMemorySize,
                         GSMEM);

    float *xz, *dx;
    bf16 *xh, *xl, *wih, *wil, *wch, *wcl, *xch, *xcl, *yh, *yl, *woh, *wol;
    cudaGetSymbolAddress((void**)&xz,  g_xz);
    cudaGetSymbolAddress((void**)&dx,  g_dx);
    cudaGetSymbolAddress((void**)&xh,  g_xh);  cudaGetSymbolAddress((void**)&xl,  g_xl);
    cudaGetSymbolAddress((void**)&wih, g_wih); cudaGetSymbolAddress((void**)&wil, g_wil);
    cudaGetSymbolAddress((void**)&wch, g_wch); cudaGetSymbolAddress((void**)&wcl, g_wcl);
    cudaGetSymbolAddress((void**)&xch, g_xch); cudaGetSymbolAddress((void**)&xcl, g_xcl);
    cudaGetSymbolAddress((void**)&yh,  g_yh);  cudaGetSymbolAddress((void**)&yl,  g_yl);
    cudaGetSymbolAddress((void**)&woh, g_woh); cudaGetSymbolAddress((void**)&wol, g_wol);

    // fused prep: splits + weight pack
    prep_k<<<(N_PREP + 255)/256, 256>>>(x, W_in, W_out, W_dt, W_x);

    // xz = x @ W_in^T
    gemm_mma<<<dim3(N_XZ/128, M_ROWS/128), 256, GSMEM>>>(
        xh, xl, wih, wil, xz, M_ROWS, N_XZ, DM);
    // xc = silu(conv(xz[:, :di]))
    conv_silu_k<<<(M_ROWS*DI + 255)/256, 256>>>(W_conv);
    // dx = xc @ [W_dt;W_x;0]^T
    gemm_mma<<<dim3(N_COMB/128, M_ROWS/128), 256, GSMEM>>>(
        xch, xcl, wch, wcl, dx, M_ROWS, N_COMB, DI);
    // chunked selective scan
    scan_a<<<dim3(DI/128, CCH, BATCH), 128>>>(A_log, b_dt);
    scan_b<<<dim3(DI/128, BATCH), 128>>>();
    scan_c<<<dim3(DI/128, CCH, BATCH), 128>>>(A_log, Dp, b_dt);
    // out = y @ W_out^T
    gemm_mma<<<dim3(DM/128, M_ROWS/128), 256, GSMEM>>>(
        yh, yl, woh, wol, out, M_ROWS, DM, DI);
}

// round 5
// speedup vs baseline: 2.8825x; 1.1134x over previous
#include <cuda_runtime.h>
#include <cuda_bf16.h>
#include <cuda_fp16.h>
#include <math.h>
#include <stdint.h>

// ---------------- problem sizes ----------------
#define L_SEQ  2048
#define BATCH  2
#define DM     768
#define DI     1536
#define DS     16
#define M_ROWS (BATCH * L_SEQ)   // 4096
#define N_XZ   (2 * DI)          // 3072
#define N_COMB 1664              // 1536 + 32, padded to 13*128
#define CCH    32                // scan chunks
#define CL     64                // chunk length
#define SPL_OFF ((size_t)M_ROWS * N_COMB)   // split-K partial stride

typedef __nv_bfloat16 bf16;

// ---------------- scratch globals ----------------
__device__ __align__(128) float g_xz[M_ROWS * N_XZ];
__device__ __align__(128) float g_dx2[2 * M_ROWS * N_COMB];   // split-K partials
__device__ __align__(128) float g_xc[M_ROWS * DI];
__device__ __align__(128) float g_p [M_ROWS * DI];
__device__ __align__(128) float g_yp[M_ROWS * DI];

__device__ __align__(128) bf16 g_xh [M_ROWS * DM],  g_xl [M_ROWS * DM];
__device__ __align__(128) bf16 g_wih[N_XZ * DM],    g_wil[N_XZ * DM];
__device__ __align__(128) bf16 g_wch[N_COMB * DI],  g_wcl[N_COMB * DI];
__device__ __align__(128) bf16 g_xch[M_ROWS * DI],  g_xcl[M_ROWS * DI];
__device__ __align__(128) __half g_y16 [M_ROWS * DI];
__device__ __align__(128) __half g_wo16[DM * DI];

__device__ __align__(128) float g_cdec[BATCH * CCH * DS * DI];
__device__ __align__(128) float g_hend[BATCH * CCH * DS * DI];
__device__ __align__(128) float g_h0  [BATCH * CCH * DS * DI];

// ---------------- PTX helpers (plain sm_80+ PTX; NO tcgen05) --------
__device__ __forceinline__ uint32_t smem_u32(const void* p) {
    uint32_t a;
    asm("{ .reg .u64 t; cvta.to.shared.u64 t, %1; cvt.u32.u64 %0, t; }" : "=r"(a) : "l"(p));
    return a;
}
#define CP_ASYNC16(dst, src) \
    asm volatile("cp.async.cg.shared.global [%0], [%1], 16;" :: "r"(dst), "l"(src))
#define CP_COMMIT() asm volatile("cp.async.commit_group;")
#define CP_WAIT(n)  asm volatile("cp.async.wait_group %0;" :: "n"(n))
#define LDSM4(r0, r1, r2, r3, a) \
    asm volatile("ldmatrix.sync.aligned.m8n8.x4.shared.b16 {%0,%1,%2,%3}, [%4];" \
                 : "=r"(r0), "=r"(r1), "=r"(r2), "=r"(r3) : "r"(a))
#define MMA_BF16(c, a, b0, b1) \
    asm volatile("mma.sync.aligned.m16n8k16.row.col.f32.bf16.bf16.f32 " \
                 "{%0,%1,%2,%3}, {%4,%5,%6,%7}, {%8,%9}, {%0,%1,%2,%3};" \
                 : "+f"((c)[0]), "+f"((c)[1]), "+f"((c)[2]), "+f"((c)[3]) \
                 : "r"((a)[0]), "r"((a)[1]), "r"((a)[2]), "r"((a)[3]), \
                   "r"(b0), "r"(b1))
#define MMA_FP16(c, a, b0, b1) \
    asm volatile("mma.sync.aligned.m16n8k16.row.col.f32.f16.f16.f32 " \
                 "{%0,%1,%2,%3}, {%4,%5,%6,%7}, {%8,%9}, {%0,%1,%2,%3};" \
                 : "+f"((c)[0]), "+f"((c)[1]), "+f"((c)[2]), "+f"((c)[3]) \
                 : "r"((a)[0]), "r"((a)[1]), "r"((a)[2]), "r"((a)[3]), \
                   "r"(b0), "r"(b1))

// ---------------- HMMA bf16x3 GEMM (optionally split-K via blockIdx.z) ----
// 128x128 tile, BK=32; SMEM rows padded to 40 bf16 (80B); 2-stage cp.async;
// 3 mma terms: hi*hi + hi*lo + lo*hi. 2 CTAs/SM via 128-reg cap.
#define TILE_B   10240            // 128 rows * 80 bytes
#define STAGE_B  (4 * TILE_B)     // Ah, Al, Bh, Bl
#define GSMEM    (2 * STAGE_B)    // 81920

__global__ __launch_bounds__(256, 2)
void gemm_mma(const bf16* __restrict__ Ah, const bf16* __restrict__ Al,
              const bf16* __restrict__ Bh, const bf16* __restrict__ Bl,
              float* __restrict__ C, int M, int N, int K, int klen) {
    extern __shared__ __align__(128) char smem[];
    const uint32_t sb = smem_u32(smem);
    const int tid  = threadIdx.x;
    const int lane = tid & 31;
    const int wid  = tid >> 5;
    const int wm   = wid & 3;          // 4 warps in M
    const int wn   = wid >> 2;         // 2 warps in N
    const int bm   = blockIdx.y * 128;
    const int bn   = blockIdx.x * 128;
    const int kstart = blockIdx.z * klen;
    C += (size_t)blockIdx.z * M * N;

    const bf16* srcs[4] = { Ah + (size_t)bm * K + kstart,
                            Al + (size_t)bm * K + kstart,
                            Bh + (size_t)bn * K + kstart,
                            Bl + (size_t)bn * K + kstart };

    int lt_t[8], lt_r[8]; uint32_t lt_o[8];
#pragma unroll
    for (int i = 0; i < 8; i++) {
        int c = i * 256 + tid;
        int t = c >> 9, w = c & 511, r = w >> 2, j = w & 3;
        lt_t[i] = t; lt_r[i] = r;
        lt_o[i] = (uint32_t)(t * TILE_B + r * 80 + j * 16);
    }

    float acc[2][8][4];
#pragma unroll
    for (int mt = 0; mt < 2; mt++)
#pragma unroll
        for (int nt = 0; nt < 8; nt++)
#pragma unroll
            for (int q = 0; q < 4; q++) acc[mt][nt][q] = 0.f;

    const uint32_t a_off = (uint32_t)((lane & 15) * 80 + (lane >> 4) * 16);
    const uint32_t b_off = (uint32_t)((((lane >> 4) << 3) + (lane & 7)) * 80 +
                                      ((lane >> 3) & 1) * 16);

    const int NC = klen >> 5;

    {
#pragma unroll
        for (int i = 0; i < 8; i++) {
            int c = i * 256 + tid; int j = c & 3;
            CP_ASYNC16(sb + lt_o[i], srcs[lt_t[i]] + (size_t)lt_r[i] * K + j * 8);
        }
        CP_COMMIT();
    }

    for (int it = 0; it < NC; it++) {
        if (it + 1 < NC) {
            const uint32_t stb = sb + ((it + 1) & 1) * STAGE_B;
            const int k0 = (it + 1) << 5;
#pragma unroll
            for (int i = 0; i < 8; i++) {
                int c = i * 256 + tid; int j = c & 3;
                CP_ASYNC16(stb + lt_o[i], srcs[lt_t[i]] + (size_t)lt_r[i] * K + k0 + j * 8);
            }
            CP_COMMIT();
            CP_WAIT(1);
        } else {
            CP_WAIT(0);
        }
        __syncthreads();

        const uint32_t st = sb + (it & 1) * STAGE_B;
        const uint32_t aHb = st + 0 * TILE_B + wm * 32 * 80 + a_off;
        const uint32_t aLb = st + 1 * TILE_B + wm * 32 * 80 + a_off;
        const uint32_t bHb = st + 2 * TILE_B + wn * 64 * 80 + b_off;
        const uint32_t bLb = st + 3 * TILE_B + wn * 64 * 80 + b_off;

#pragma unroll
        for (int kk = 0; kk < 2; kk++) {
            const uint32_t ko = kk * 32;
            uint32_t ah[2][4], al[2][4];
#pragma unroll
            for (int mt = 0; mt < 2; mt++) {
                LDSM4(ah[mt][0], ah[mt][1], ah[mt][2], ah[mt][3],
                      aHb + mt * 16 * 80 + ko);
                LDSM4(al[mt][0], al[mt][1], al[mt][2], al[mt][3],
                      aLb + mt * 16 * 80 + ko);
            }
#pragma unroll
            for (int half = 0; half < 2; half++) {
                uint32_t bh[2][4], bl[2][4];
#pragma unroll
                for (int u = 0; u < 2; u++) {
                    const int bt = half * 2 + u;
                    LDSM4(bh[u][0], bh[u][1], bh[u][2], bh[u][3],
                          bHb + bt * 16 * 80 + ko);
                    LDSM4(bl[u][0], bl[u][1], bl[u][2], bl[u][3],
                          bLb + bt * 16 * 80 + ko);
                }
#pragma unroll
                for (int mt = 0; mt < 2; mt++)
#pragma unroll
                    for (int v = 0; v < 4; v++) {
                        const int nt = half * 4 + v;
                        const int u = v >> 1, hh = (v & 1) << 1;
                        MMA_BF16(acc[mt][nt], ah[mt], bh[u][hh], bh[u][hh + 1]);
                        MMA_BF16(acc[mt][nt], ah[mt], bl[u][hh], bl[u][hh + 1]);
                        MMA_BF16(acc[mt][nt], al[mt], bh[u][hh], bh[u][hh + 1]);
                    }
            }
        }
        __syncthreads();
    }

    const int r0 = bm + wm * 32 + (lane >> 2);
    const int c0 = bn + wn * 64 + (lane & 3) * 2;
#pragma unroll
    for (int mt = 0; mt < 2; mt++)
#pragma unroll
        for (int nt = 0; nt < 8; nt++) {
            float* p0 = C + (size_t)(r0 + mt * 16) * N + c0 + nt * 8;
            *(float2*)p0                   = make_float2(acc[mt][nt][0], acc[mt][nt][1]);
            *(float2*)(p0 + (size_t)8 * N) = make_float2(acc[mt][nt][2], acc[mt][nt][3]);
        }
}

// ---------------- fp16 single-term GEMM (final projection) ----------------
// 64x128 tile, BK=32, 256 threads (8 warps: 2M x 4N), 2-stage cp.async.
#define T3_TILE_A 5120            // 64 * 80
#define T3_STAGE  15360           // A(5120) + B(10240)
#define T3_SMEM   (2 * T3_STAGE)  // 30720

__global__ __launch_bounds__(256, 3)
void gemm_fp16(const __half* __restrict__ A, const __half* __restrict__ B,
               float* __restrict__ C, int M, int N, int K) {
    extern __shared__ __align__(128) char smem[];
    const uint32_t sb = smem_u32(smem);
    const int tid  = threadIdx.x;
    const int lane = tid & 31;
    const int wid  = tid >> 5;
    const int wm   = wid & 1;          // 2 warps in M
    const int wn   = wid >> 1;         // 4 warps in N
    const int bm   = blockIdx.y * 64;
    const int bn   = blockIdx.x * 128;

    const __half* srcA = A + (size_t)bm * K;
    const __half* srcB = B + (size_t)bn * K;

    float acc[2][4][4];
#pragma unroll
    for (int mt = 0; mt < 2; mt++)
#pragma unroll
        for (int nt = 0; nt < 4; nt++)
#pragma unroll
            for (int q = 0; q < 4; q++) acc[mt][nt][q] = 0.f;

    const uint32_t a_off = (uint32_t)((lane & 15) * 80 + (lane >> 4) * 16);
    const uint32_t b_off = (uint32_t)((((lane >> 4) << 3) + (lane & 7)) * 80 +
                                      ((lane >> 3) & 1) * 16);

    const int NC = K >> 5;

    // load mapping: 768 chunks of 16B per stage, 3 per thread
    auto load_stage = [&](uint32_t stb, int k0) {
#pragma unroll
        for (int i = 0; i < 3; i++) {
            int c = i * 256 + tid;
            if (c < 256) {
                int r = c >> 2, j = c & 3;
                CP_ASYNC16(stb + r * 80 + j * 16,
                           srcA + (size_t)r * K + k0 + j * 8);
            } else {
                int c2 = c - 256;
                int r = c2 >> 2, j = c2 & 3;
                CP_ASYNC16(stb + T3_TILE_A + r * 80 + j * 16,
                           srcB + (size_t)r * K + k0 + j * 8);
            }
        }
        CP_COMMIT();
    };

    load_stage(sb, 0);

    for (int it = 0; it < NC; it++) {
        if (it + 1 < NC) {
            load_stage(sb + ((it + 1) & 1) * T3_STAGE, (it + 1) << 5);
            CP_WAIT(1);
        } else {
            CP_WAIT(0);
        }
        __syncthreads();

        const uint32_t st = sb + (it & 1) * T3_STAGE;
        const uint32_t aB = st + wm * 32 * 80 + a_off;
        const uint32_t bB = st + T3_TILE_A + wn * 32 * 80 + b_off;

#pragma unroll
        for (int kk = 0; kk < 2; kk++) {
            const uint32_t ko = kk * 32;
            uint32_t ah[2][4], bb[2][4];
#pragma unroll
            for (int mt = 0; mt < 2; mt++)
                LDSM4(ah[mt][0], ah[mt][1], ah[mt][2], ah[mt][3],
                      aB + mt * 16 * 80 + ko);
#pragma unroll
            for (int bt = 0; bt < 2; bt++)
                LDSM4(bb[bt][0], bb[bt][1], bb[bt][2], bb[bt][3],
                      bB + bt * 16 * 80 + ko);
#pragma unroll
            for (int mt = 0; mt < 2; mt++)
#pragma unroll
                for (int nt = 0; nt < 4; nt++) {
                    const int bt = nt >> 1, hh = (nt & 1) << 1;
                    MMA_FP16(acc[mt][nt], ah[mt], bb[bt][hh], bb[bt][hh + 1]);
                }
        }
        __syncthreads();
    }

    const int r0 = bm + wm * 32 + (lane >> 2);
    const int c0 = bn + wn * 32 + (lane & 3) * 2;
#pragma unroll
    for (int mt = 0; mt < 2; mt++)
#pragma unroll
        for (int nt = 0; nt < 4; nt++) {
            float* p0 = C + (size_t)(r0 + mt * 16) * N + c0 + nt * 8;
            *(float2*)p0                   = make_float2(acc[mt][nt][0], acc[mt][nt][1]);
            *(float2*)(p0 + (size_t)8 * N) = make_float2(acc[mt][nt][2], acc[mt][nt][3]);
        }
}

// ---------------- fp32 -> bf16 hi/lo split ----------------
__device__ __forceinline__ void split_bf16(float v, bf16& h, bf16& l) {
    h = __float2bfloat16_rn(v);
    l = __float2bfloat16_rn(v - __bfloat162float(h));
}

// fused prep: split x, W_in; W_out->fp16; pack+split [W_dt;W_x;0]
#define N_JOB0 (M_ROWS * DM)
#define N_JOB1 (N_XZ * DM)
#define N_JOB2 (DM * DI)
#define N_JOB3 (N_COMB * DI)
#define N_PREP (N_JOB0 + N_JOB1 + N_JOB2 + N_JOB3)
__global__ void prep_k(const float* __restrict__ x, const float* __restrict__ Win,
                       const float* __restrict__ Wout,
                       const float* __restrict__ Wdt, const float* __restrict__ Wx) {
    int idx = blockIdx.x * 256 + threadIdx.x;
    if (idx < N_JOB0) {
        split_bf16(x[idx], g_xh[idx], g_xl[idx]);
        return;
    }
    idx -= N_JOB0;
    if (idx < N_JOB1) {
        split_bf16(Win[idx], g_wih[idx], g_wil[idx]);
        return;
    }
    idx -= N_JOB1;
    if (idx < N_JOB2) {
        g_wo16[idx] = __float2half_rn(Wout[idx]);
        return;
    }
    idx -= N_JOB2;
    if (idx < N_JOB3) {
        int row = idx / DI, col = idx - row * DI;
        float v = 0.f;
        if (row < DI)           v = Wdt[idx];
        else if (row < DI + 32) v = Wx[(row - DI) * DI + col];
        split_bf16(v, g_wch[idx], g_wcl[idx]);
    }
}

// ---------------- conv + SiLU (fp32 + bf16 split outputs) ----------------
__global__ void conv_silu_k(const float* __restrict__ Wc) {
    int idx = blockIdx.x * 256 + threadIdx.x;
    if (idx >= M_ROWS * DI) return;
    int d = idx % DI, m = idx / DI, l = m & (L_SEQ - 1);
    float w0 = Wc[d*4+0], w1 = Wc[d*4+1], w2 = Wc[d*4+2], w3 = Wc[d*4+3];
    float s = g_xz[(size_t)m * N_XZ + d] * w3;
    if (l >= 1) s = fmaf(g_xz[(size_t)(m-1) * N_XZ + d], w2, s);
    if (l >= 2) s = fmaf(g_xz[(size_t)(m-2) * N_XZ + d], w1, s);
    if (l >= 3) s = fmaf(g_xz[(size_t)(m-3) * N_XZ + d], w0, s);
    float v = __fdividef(s, 1.f + __expf(-s));
    g_xc[idx] = v;
    split_bf16(v, g_xch[idx], g_xcl[idx]);
}

// ---------------- scan helpers ----------------
__device__ __forceinline__ void pow16(float p, float* pw) {
    pw[0]=p;          pw[1]=p*p;        pw[2]=pw[1]*p;     pw[3]=pw[1]*pw[1];
    pw[4]=pw[3]*p;    pw[5]=pw[3]*pw[1];pw[6]=pw[3]*pw[2]; pw[7]=pw[3]*pw[3];
    pw[8]=pw[7]*p;    pw[9]=pw[7]*pw[1];pw[10]=pw[7]*pw[2];pw[11]=pw[7]*pw[3];
    pw[12]=pw[7]*pw[4];pw[13]=pw[7]*pw[5];pw[14]=pw[7]*pw[6];pw[15]=pw[7]*pw[7];
}
__device__ __forceinline__ bool geo_check(const float* Alog, float* A) {
#pragma unroll
    for (int s = 0; s < DS; s++) A[s] = -__expf(Alog[s]);
    bool geo = true;
#pragma unroll
    for (int s = 0; s < DS; s++)
        geo = geo && (fabsf(A[s] - (float)(s + 1) * A[0]) <= 1e-5f * fabsf(A[s]));
    return geo;
}
__device__ __forceinline__ float softplus_f(float x) {
    return (x > 20.f) ? x : log1pf(__expf(x));
}
__device__ __forceinline__ float dx_sum(size_t idx) {
    return g_dx2[idx] + g_dx2[SPL_OFF + idx];
}

// ---------------- scan phase A: local scans ----------------
__global__ __launch_bounds__(128)
void scan_a(const float* __restrict__ Alog, const float* __restrict__ bdt) {
    __shared__ float sBC[CL * 32];
    const int d = blockIdx.x * 128 + threadIdx.x;
    const int c = blockIdx.y, b = blockIdx.z;
    const int m0 = b * L_SEQ + c * CL;
    for (int e = threadIdx.x; e < CL * 32; e += 128) {
        int l = e >> 5, q = e & 31;
        sBC[e] = dx_sum((size_t)(m0 + l) * N_COMB + DI + q);
    }
    __syncthreads();

    float A[DS];
    const bool geo = geo_check(Alog, A);
    const float bd = bdt[d];
    float h[DS];
#pragma unroll
    for (int s = 0; s < DS; s++) h[s] = 0.f;
    const size_t base = ((size_t)(b * CCH + c) * DS) * DI + d;

    if (geo) {
        const float A0 = A[0];
        float pp = 1.f;
        for (int l = 0; l < CL; l++) {
            const size_t m = m0 + l;
            float dt = softplus_f(dx_sum(m * N_COMB + d) + bd);
            float p = __expf(A0 * dt);
            g_p[m * DI + d] = p;
            pp *= p;
            float pw[DS]; pow16(p, pw);
            float y0=0.f, y1=0.f, y2=0.f, y3=0.f;
#pragma unroll
            for (int s = 0; s < DS; s++) {
                h[s] = fmaf(pw[s], h[s], dt * sBC[l * 32 + s]);
                float t = h[s] * sBC[l * 32 + 16 + s];
                if ((s&3)==0) y0+=t; else if ((s&3)==1) y1+=t;
                else if ((s&3)==2) y2+=t; else y3+=t;
            }
            g_yp[m * DI + d] = (y0 + y1) + (y2 + y3);
        }
        float dw[DS]; pow16(pp, dw);
#pragma unroll
        for (int s = 0; s < DS; s++) {
            g_cdec[base + (size_t)s * DI] = dw[s];
            g_hend[base + (size_t)s * DI] = h[s];
        }
    } else {
        float dec[DS];
#pragma unroll
        for (int s = 0; s < DS; s++) dec[s] = 1.f;
        for (int l = 0; l < CL; l++) {
            const size_t m = m0 + l;
            float dt = softplus_f(dx_sum(m * N_COMB + d) + bd);
            float y0=0.f, y1=0.f, y2=0.f, y3=0.f;
#pragma unroll
            for (int s = 0; s < DS; s++) {
                float dA = __expf(A[s] * dt);
                dec[s] *= dA;
                h[s] = fmaf(dA, h[s], dt * sBC[l * 32 + s]);
                float t = h[s] * sBC[l * 32 + 16 + s];
                if ((s&3)==0) y0+=t; else if ((s&3)==1) y1+=t;
                else if ((s&3)==2) y2+=t; else y3+=t;
            }
            g_yp[m * DI + d] = (y0 + y1) + (y2 + y3);
        }
#pragma unroll
        for (int s = 0; s < DS; s++) {
            g_cdec[base + (size_t)s * DI] = dec[s];
            g_hend[base + (size_t)s * DI] = h[s];
        }
    }
}

// ---------------- scan phase B: chunk combine ----------------
__global__ __launch_bounds__(128)
void scan_b() {
    const int d = blockIdx.x * 128 + threadIdx.x;
    const int b = blockIdx.y;
    float H[DS];
#pragma unroll
    for (int s = 0; s < DS; s++) H[s] = 0.f;
    for (int c = 0; c < CCH; c++) {
        const size_t base = ((size_t)(b * CCH + c) * DS) * DI + d;
#pragma unroll
        for (int s = 0; s < DS; s++) {
            g_h0[base + (size_t)s * DI] = H[s];
            H[s] = fmaf(g_cdec[base + (size_t)s * DI], H[s],
                        g_hend[base + (size_t)s * DI]);
        }
    }
}

// ---------------- scan phase C: correction + gate + fp16 out ----------------
__global__ __launch_bounds__(128)
void scan_c(const float* __restrict__ Alog, const float* __restrict__ Dp,
            const float* __restrict__ bdt) {
    __shared__ float sC[CL * 16];
    const int d = blockIdx.x * 128 + threadIdx.x;
    const int c = blockIdx.y, b = blockIdx.z;
    const int m0 = b * L_SEQ + c * CL;
    for (int e = threadIdx.x; e < CL * 16; e += 128) {
        int l = e >> 4, q = e & 15;
        sC[e] = dx_sum((size_t)(m0 + l) * N_COMB + DI + 16 + q);
    }
    __syncthreads();

    float A[DS];
    const bool geo = geo_check(Alog, A);
    const float Dd = Dp[d];
    const float bd = bdt[d];
    float H0[DS];
    const size_t base = ((size_t)(b * CCH + c) * DS) * DI + d;
#pragma unroll
    for (int s = 0; s < DS; s++) H0[s] = g_h0[base + (size_t)s * DI];

    if (geo) {
        float run = 1.f;
        for (int l = 0; l < CL; l++) {
            const size_t m = m0 + l;
            run *= g_p[m * DI + d];
            float rw[DS]; pow16(run, rw);
            float corr = 0.f;
#pragma unroll
            for (int s = 0; s < DS; s++)
                corr = fmaf(rw[s] * H0[s], sC[l * 16 + s], corr);
            float y = g_yp[m * DI + d] + corr;
            float z = g_xz[m * N_XZ + DI + d];
            float o = (y + Dd * g_xc[m * DI + d]) *
                      __fdividef(z, 1.f + __expf(-z));
            g_y16[m * DI + d] = __float2half_rn(o);
        }
    } else {
        float run[DS];
#pragma unroll
        for (int s = 0; s < DS; s++) run[s] = 1.f;
        for (int l = 0; l < CL; l++) {
            const size_t m = m0 + l;
            float dt = softplus_f(dx_sum(m * N_COMB + d) + bd);
            float corr = 0.f;
#pragma unroll
            for (int s = 0; s < DS; s++) {
                run[s] *= __expf(A[s] * dt);
                corr = fmaf(run[s] * H0[s], sC[l * 16 + s], corr);
            }
            float y = g_yp[m * DI + d] + corr;
            float z = g_xz[m * N_XZ + DI + d];
            float o = (y + Dd * g_xc[m * DI + d]) *
                      __fdividef(z, 1.f + __expf(-z));
            g_y16[m * DI + d] = __float2half_rn(o);
        }
    }
}

// ---------------- launch ----------------
extern "C" void kernel_launch(void* const* d_in, const int* in_sizes, int n_in,
                              void* d_out, int out_size) {
    const float* x      = (const float*)d_in[0];
    const float* W_in   = (const float*)d_in[1];
    const float* W_conv = (const float*)d_in[2];
    const float* W_x    = (const float*)d_in[3];
    const float* W_dt   = (const float*)d_in[4];
    const float* b_dt   = (const float*)d_in[5];
    const float* A_log  = (const float*)d_in[6];
    const float* Dp     = (const float*)d_in[7];
    const float* W_out  = (const float*)d_in[8];
    float* out = (float*)d_out;

    cudaFuncSetAttribute(gemm_mma, cudaFuncAttributeMaxDynamicSharedMemorySize,
                         GSMEM);
    cudaFuncSetAttribute(gemm_fp16, cudaFuncAttributeMaxDynamicSharedMemorySize,
                         T3_SMEM);

    float *xz, *dx2;
    bf16 *xh, *xl, *wih, *wil, *wch, *wcl, *xch, *xcl;
    __half *y16, *wo16;
    cudaGetSymbolAddress((void**)&xz,   g_xz);
    cudaGetSymbolAddress((void**)&dx2,  g_dx2);
    cudaGetSymbolAddress((void**)&xh,   g_xh);  cudaGetSymbolAddress((void**)&xl,   g_xl);
    cudaGetSymbolAddress((void**)&wih,  g_wih); cudaGetSymbolAddress((void**)&wil,  g_wil);
    cudaGetSymbolAddress((void**)&wch,  g_wch); cudaGetSymbolAddress((void**)&wcl,  g_wcl);
    cudaGetSymbolAddress((void**)&xch,  g_xch); cudaGetSymbolAddress((void**)&xcl,  g_xcl);
    cudaGetSymbolAddress((void**)&y16,  g_y16); cudaGetSymbolAddress((void**)&wo16, g_wo16);

    // fused prep: splits + weight pack + W_out fp16
    prep_k<<<(N_PREP + 255)/256, 256>>>(x, W_in, W_out, W_dt, W_x);

    // xz = x @ W_in^T
    gemm_mma<<<dim3(N_XZ/128, M_ROWS/128, 1), 256, GSMEM>>>(
        xh, xl, wih, wil, xz, M_ROWS, N_XZ, DM, DM);
    // xc = silu(conv(xz[:, :di]))
    conv_silu_k<<<(M_ROWS*DI + 255)/256, 256>>>(W_conv);
    // dx = xc @ [W_dt;W_x;0]^T  (split-K 2, partials summed in scan kernels)
    gemm_mma<<<dim3(N_COMB/128, M_ROWS/128, 2), 256, GSMEM>>>(
        xch, xcl, wch, wcl, dx2, M_ROWS, N_COMB, DI, DI/2);
    // chunked selective scan
    scan_a<<<dim3(DI/128, CCH, BATCH), 128>>>(A_log, b_dt);
    scan_b<<<dim3(DI/128, BATCH), 128>>>();
    scan_c<<<dim3(DI/128, CCH, BATCH), 128>>>(A_log, Dp, b_dt);
    // out = y @ W_out^T  (fp16 single-term)
    gemm_fp16<<<dim3(DM/128, M_ROWS/64), 256, T3_SMEM>>>(
        y16, wo16, out, M_ROWS, DM, DI);
}